// round 16
// baseline (speedup 1.0000x reference)
#include <cuda_runtime.h>
#include <cuda_fp16.h>
#include <cstdint>

#define N_NODES 50000
#define N_EDGES 800000
#define IN_F    256
#define OUT_F   64
#define E4      (N_EDGES / 4)          // 200000
#define GEMM_BLOCKS 391                // ceil(50000/128)
#define CSR_BLOCKS  160
#define NB (GEMM_BLOCKS + CSR_BLOCKS)  // 551
#define SBH 264                        // sB stride in halves (LDSM conflict-free)
#define AWS 24                         // per-warp A slab row stride in halves

// Scratch (device globals: allocation-guard compliant, zero-init at load)
__device__ __half g_hw[(size_t)N_NODES * OUT_F];  // projected*norm feats (fp16)
__device__ int    g_deg[N_NODES];                 // in-degree (zeroed by aggregate)
__device__ int    g_start[N_NODES];               // CSR row starts
__device__ int    g_slot[N_EDGES];                // per-edge slot within dst bucket
__device__ int    g_esrc[N_EDGES];                // src ids bucketed by dst
__device__ int    g_bsum[CSR_BLOCKS];             // CSR per-block sums
__device__ int    g_boff[CSR_BLOCKS];             // scanned block offsets
// Sense-reversing barrier state for the CSR sub-barrier (zero-init).
__device__ unsigned g_cnt_csr, g_sense_csr;

// ---------------------------------------------------------------------------
// Sense-reversing barrier among the CSR-role blocks ONLY.  Deadlock-free:
// GEMM blocks never wait, always retire, freeing slots for pending CSR
// blocks, so all CSR_BLOCKS arrivals eventually happen.
// ---------------------------------------------------------------------------
__device__ __forceinline__ void bar_csr(unsigned& ls) {
    __threadfence();
    __syncthreads();
    if (threadIdx.x == 0) {
        ls ^= 1u;
        if (atomicAdd(&g_cnt_csr, 1u) == CSR_BLOCKS - 1u) {
            atomicExch(&g_cnt_csr, 0u);
            atomicExch(&g_sense_csr, ls);
        } else {
            while (atomicAdd(&g_sense_csr, 0u) != ls) __nanosleep(64);
        }
    }
    __syncthreads();
    __threadfence();
}

// ---------------------------------------------------------------------------
// Fused kernel: GEMM role (blocks 0..390, R13 validated body) and CSR role
// (blocks 391..550: hist -> scan -> fill with CSR-only sub-barriers).
// Heterogeneous blocks share one register/smem class -> true co-scheduling.
// ---------------------------------------------------------------------------
__global__ __launch_bounds__(256, 3) void fused_gemm_csr_kernel(
    const float* __restrict__ h,
    const float* __restrict__ w,
    const float* __restrict__ norm,
    const int4*  __restrict__ src4,
    const int4*  __restrict__ dst4)
{
    __shared__ alignas(16) __half sB[64 * SBH];            // 33792 B
    __shared__ alignas(16) __half sAw[8][2][16 * AWS];     // 12288 B
    __shared__ int sScan[256];                             //  1024 B

    const int bid  = blockIdx.x;
    const int tid  = threadIdx.x;
    const int warp = tid >> 5;
    const int lane = tid & 31;
    const unsigned FULL = 0xFFFFFFFFu;

    if (bid >= GEMM_BLOCKS) {
        // ===================== CSR role (160 blocks) =====================
        const int cb = bid - GEMM_BLOCKS;          // 0..159
        const int stride = CSR_BLOCKS * 256;       // 40960

        unsigned lsCsr = 0;
        if (tid == 0) lsCsr = atomicAdd(&g_sense_csr, 0u);

        // --- hist + slot recording (grid-stride over int4 edges)
        for (int i = cb * 256 + tid; i < E4; i += stride) {
            const int4 d = __ldg(dst4 + i);
            int4 sl;
            sl.x = atomicAdd(&g_deg[d.x], 1);
            sl.y = atomicAdd(&g_deg[d.y], 1);
            sl.z = atomicAdd(&g_deg[d.z], 1);
            sl.w = atomicAdd(&g_deg[d.w], 1);
            ((int4*)g_slot)[i] = sl;
        }
        bar_csr(lsCsr);

        // --- scan A: 2 nodes per thread, block scan, record block sum
        const int nb = (cb * 256 + tid) * 2;       // node base (max 81918)
        const int v0 = (nb + 0 < N_NODES) ? g_deg[nb + 0] : 0;
        const int v1 = (nb + 1 < N_NODES) ? g_deg[nb + 1] : 0;
        const int s2 = v0 + v1;
        sScan[tid] = s2;
        __syncthreads();
        for (int off = 1; off < 256; off <<= 1) {
            int x = (tid >= off) ? sScan[tid - off] : 0;
            __syncthreads();
            sScan[tid] += x;
            __syncthreads();
        }
        const int excl = sScan[tid] - s2;
        if (tid == 255) g_bsum[cb] = sScan[255];
        bar_csr(lsCsr);

        // --- scan B: block 0 scans the 160 block sums (exclusive)
        if (cb == 0) {
            const int v = (tid < CSR_BLOCKS) ? g_bsum[tid] : 0;
            sScan[tid] = v;
            __syncthreads();
            for (int off = 1; off < 256; off <<= 1) {
                int x = (tid >= off) ? sScan[tid - off] : 0;
                __syncthreads();
                sScan[tid] += x;
                __syncthreads();
            }
            if (tid < CSR_BLOCKS) g_boff[tid] = sScan[tid] - v;
        }
        bar_csr(lsCsr);

        // --- scan C: write row starts
        int basep = g_boff[cb] + excl;
        if (nb + 0 < N_NODES) { g_start[nb + 0] = basep; basep += v0; }
        if (nb + 1 < N_NODES) { g_start[nb + 1] = basep; }
        bar_csr(lsCsr);

        // --- atomic-free fill
        for (int i = cb * 256 + tid; i < E4; i += stride) {
            const int4 d  = __ldg(dst4 + i);
            const int4 sl = ((const int4*)g_slot)[i];
            const int4 s  = __ldg(src4 + i);
            g_esrc[g_start[d.x] + sl.x] = s.x;
            g_esrc[g_start[d.y] + sl.y] = s.y;
            g_esrc[g_start[d.z] + sl.z] = s.z;
            g_esrc[g_start[d.w] + sl.w] = s.w;
        }
        return;
    }

    // ===================== GEMM role (R13 validated body) =====================
    const int g = lane >> 2;
    const int t = lane & 3;
    const int row0 = bid * 128;

    // stage full W once: w[k][n] (f32) -> sB[n][k] (f16)
#pragma unroll
    for (int i = 0; i < 16; i++) {
        const int fid = tid + 256 * i;
        const int k   = fid >> 4;
        const int n0  = (fid & 15) * 4;
        const float4 v = __ldg((const float4*)w + fid);
        sB[(n0 + 0) * SBH + k] = __float2half_rn(v.x);
        sB[(n0 + 1) * SBH + k] = __float2half_rn(v.y);
        sB[(n0 + 2) * SBH + k] = __float2half_rn(v.z);
        sB[(n0 + 3) * SBH + k] = __float2half_rn(v.w);
    }
    __syncthreads();

    const int r0 = row0 + warp * 16 + g;
    const int r1 = r0 + 8;
    const bool ok0 = (r0 < N_NODES);
    const bool ok1 = (r1 < N_NODES);
    const float* pA0 = h + (size_t)r0 * IN_F + 4 * t;
    const float* pA1 = h + (size_t)r1 * IN_F + 4 * t;

    const uint32_t rowp = (uint32_t)(((lane >> 3) & 1) * 8 + (lane & 7));
    const uint32_t acol = (uint32_t)((lane >> 4) * 8);
    uint32_t aSlab[2];
#pragma unroll
    for (int st = 0; st < 2; st++)
        aSlab[st] = (uint32_t)__cvta_generic_to_shared(&sAw[warp][st][0]) +
                    (rowp * AWS + acol) * 2;

    const uint32_t sB_u = (uint32_t)__cvta_generic_to_shared(sB);
    const uint32_t bRow = (uint32_t)((lane >> 4) * 8 + (lane & 7));
    const uint32_t bCol = (uint32_t)(((lane >> 3) & 1) * 8);
    uint32_t bAddr[4];
#pragma unroll
    for (int np = 0; np < 4; np++)
        bAddr[np] = sB_u + ((np * 16 + bRow) * SBH + bCol) * 2;

    float acc[8][4];
#pragma unroll
    for (int i = 0; i < 8; i++)
#pragma unroll
        for (int j = 0; j < 4; j++) acc[i][j] = 0.f;

    const float4 z4 = make_float4(0.f, 0.f, 0.f, 0.f);
    float4 fR[2][2];

#define LDG_A(buf, s)                                                        \
    do {                                                                     \
        const int kb = (s) * 16;                                             \
        fR[buf][0] = ok0 ? __ldg((const float4*)(pA0 + kb)) : z4;            \
        fR[buf][1] = ok1 ? __ldg((const float4*)(pA1 + kb)) : z4;            \
    } while (0)

    LDG_A(0, 0);
    LDG_A(1, 1);

#pragma unroll
    for (int s = 0; s < 16; s++) {
        const int buf = s & 1;
        {
            __half2 p0 = __floats2half2_rn(fR[buf][0].x, fR[buf][0].y);
            __half2 p1 = __floats2half2_rn(fR[buf][0].z, fR[buf][0].w);
            __half2 q0 = __floats2half2_rn(fR[buf][1].x, fR[buf][1].y);
            __half2 q1 = __floats2half2_rn(fR[buf][1].z, fR[buf][1].w);
            uint2 u0, u1;
            u0.x = *(uint32_t*)&p0; u0.y = *(uint32_t*)&p1;
            u1.x = *(uint32_t*)&q0; u1.y = *(uint32_t*)&q1;
            *(uint2*)(&sAw[warp][buf][(g    ) * AWS + 4 * t]) = u0;
            *(uint2*)(&sAw[warp][buf][(g + 8) * AWS + 4 * t]) = u1;
        }
        if (s < 14) LDG_A(buf, s + 2);
        __syncwarp();

        uint32_t a0, a1, a2, a3;
        asm volatile(
            "ldmatrix.sync.aligned.m8n8.x4.shared.b16 {%0,%1,%2,%3}, [%4];"
            : "=r"(a0), "=r"(a1), "=r"(a2), "=r"(a3)
            : "r"(aSlab[buf]));

#pragma unroll
        for (int np = 0; np < 4; np++) {
            uint32_t b0, b1, b2, b3;
            asm volatile(
                "ldmatrix.sync.aligned.m8n8.x4.shared.b16 {%0,%1,%2,%3}, [%4];"
                : "=r"(b0), "=r"(b1), "=r"(b2), "=r"(b3)
                : "r"(bAddr[np] + s * 32));
            asm volatile(
                "mma.sync.aligned.m16n8k16.row.col.f32.f16.f16.f32 "
                "{%0,%1,%2,%3}, {%4,%5,%6,%7}, {%8,%9}, {%0,%1,%2,%3};"
                : "+f"(acc[np * 2][0]), "+f"(acc[np * 2][1]),
                  "+f"(acc[np * 2][2]), "+f"(acc[np * 2][3])
                : "r"(a0), "r"(a1), "r"(a2), "r"(a3), "r"(b0), "r"(b1));
            asm volatile(
                "mma.sync.aligned.m16n8k16.row.col.f32.f16.f16.f32 "
                "{%0,%1,%2,%3}, {%4,%5,%6,%7}, {%8,%9}, {%0,%1,%2,%3};"
                : "+f"(acc[np * 2 + 1][0]), "+f"(acc[np * 2 + 1][1]),
                  "+f"(acc[np * 2 + 1][2]), "+f"(acc[np * 2 + 1][3])
                : "r"(a0), "r"(a1), "r"(a2), "r"(a3), "r"(b2), "r"(b3));
        }
        __syncwarp();
    }

    // Epilogue: scale by norm[row], convert to fp16, store half2 pairs
    const float nv0 = ok0 ? __ldg(norm + r0) : 0.f;
    const float nv1 = ok1 ? __ldg(norm + r1) : 0.f;
    __half2* __restrict__ hw2 = (__half2*)g_hw;
#pragma unroll
    for (int nt = 0; nt < 8; nt++) {
        const int c2 = nt * 4 + t;
        if (ok0)
            hw2[(size_t)r0 * 32 + c2] =
                __floats2half2_rn(acc[nt][0] * nv0, acc[nt][1] * nv0);
        if (ok1)
            hw2[(size_t)r1 * 32 + c2] =
                __floats2half2_rn(acc[nt][2] * nv1, acc[nt][3] * nv1);
    }
}

// ---------------------------------------------------------------------------
// Aggregate (R15 validated body): 4 nodes per warp via 8-lane groups,
// LDG.128 gathers, fp32 accumulation; restores g_deg = 0.
// ---------------------------------------------------------------------------
__global__ __launch_bounds__(256) void aggregate_kernel(
    const float* __restrict__ norm,
    const float* __restrict__ bias,
    float* __restrict__ out)
{
    const unsigned FULL = 0xFFFFFFFFu;
    const int wid  = (blockIdx.x * 256 + threadIdx.x) >> 5;
    const int base = wid * 4;
    if (base >= N_NODES) return;         // N_NODES % 4 == 0: uniform per warp
    const int lane  = threadIdx.x & 31;
    const int group = lane >> 3;         // 0..3 -> node base+group
    const int fl    = lane & 7;          // 16-byte chunk within the row

    int st = 0, dg = 0;
    if (lane < 4) {
        st = g_start[base + lane];
        dg = g_deg[base + lane];
        g_deg[base + lane] = 0;          // restore invariant for next call
    }
    const int stG = __shfl_sync(FULL, st, group);
    const int dgG = __shfl_sync(FULL, dg, group);
    const int d0 = __shfl_sync(FULL, dg, 0), d1 = __shfl_sync(FULL, dg, 1);
    const int d2 = __shfl_sync(FULL, dg, 2), d3 = __shfl_sync(FULL, dg, 3);
    const int m = max(max(d0, d1), max(d2, d3));

    const uint4* __restrict__ hwq = (const uint4*)g_hw;  // 8 uint4 per row

    float acc[8];
#pragma unroll
    for (int i = 0; i < 8; i++) acc[i] = 0.f;

    for (int b = 0; b < m; b += 8) {
        const int idx = (b + fl < dgG) ? __ldg(g_esrc + stG + b + fl) : 0;
#pragma unroll
        for (int j = 0; j < 8; j++) {
            const int s = __shfl_sync(FULL, idx, (group << 3) + j);
            if (b + j < dgG) {
                const uint4 v = __ldg(hwq + (size_t)s * 8 + fl);
                const float2 p0 = __half22float2(*(const __half2*)&v.x);
                const float2 p1 = __half22float2(*(const __half2*)&v.y);
                const float2 p2 = __half22float2(*(const __half2*)&v.z);
                const float2 p3 = __half22float2(*(const __half2*)&v.w);
                acc[0] += p0.x; acc[1] += p0.y;
                acc[2] += p1.x; acc[3] += p1.y;
                acc[4] += p2.x; acc[5] += p2.y;
                acc[6] += p3.x; acc[7] += p3.y;
            }
        }
    }

    const int node = base + group;
    const float nv = __ldg(norm + node);
    const float4 bi0 = ((const float4*)bias)[fl * 2];
    const float4 bi1 = ((const float4*)bias)[fl * 2 + 1];
    float4 r0, r1;
    r0.x = fmaxf(fmaf(acc[0], nv, bi0.x), 0.f);
    r0.y = fmaxf(fmaf(acc[1], nv, bi0.y), 0.f);
    r0.z = fmaxf(fmaf(acc[2], nv, bi0.z), 0.f);
    r0.w = fmaxf(fmaf(acc[3], nv, bi0.w), 0.f);
    r1.x = fmaxf(fmaf(acc[4], nv, bi1.x), 0.f);
    r1.y = fmaxf(fmaf(acc[5], nv, bi1.y), 0.f);
    r1.z = fmaxf(fmaf(acc[6], nv, bi1.z), 0.f);
    r1.w = fmaxf(fmaf(acc[7], nv, bi1.w), 0.f);
    ((float4*)out)[(size_t)node * 16 + fl * 2]     = r0;
    ((float4*)out)[(size_t)node * 16 + fl * 2 + 1] = r1;
}

// ---------------------------------------------------------------------------
extern "C" void kernel_launch(void* const* d_in, const int* in_sizes, int n_in,
                              void* d_out, int out_size)
{
    const float* h      = (const float*)d_in[0];
    const float* norm   = (const float*)d_in[1];
    const int*   src    = (const int*)d_in[2];
    const int*   dst    = (const int*)d_in[3];
    const float* weight = (const float*)d_in[4];
    const float* bias   = (const float*)d_in[5];
    float* out = (float*)d_out;

    // 1) fused GEMM + CSR build (heterogeneous grid; CSR sub-barriers only)
    fused_gemm_csr_kernel<<<NB, 256>>>(h, weight, norm,
                                       (const int4*)src, (const int4*)dst);

    // 2) aggregation + fused epilogue (norm[dst], bias, relu)
    {
        const int warps  = N_NODES / 4;          // 12500
        const int blocks = (warps * 32 + 255) / 256;
        aggregate_kernel<<<blocks, 256>>>(norm, bias, out);
    }
}